// round 7
// baseline (speedup 1.0000x reference)
#include <cuda_runtime.h>
#include <stdint.h>

// Problem constants
#define NT    4000
#define NS    16
#define NR    512
#define NCOL  (NS * NR)        // 8192 columns
#define NCG   (NCOL / 4)       // 2048 float4 column-groups
#define NSEG  80
#define SEG_LEN (NT / NSEG)    // 50
#define TPB   256
#define XBLK  (NCG / TPB)      // 8
#define NBLK  (XBLK * NSEG)    // 640 blocks total
#define COLS_PER_THREAD (NCOL / TPB)  // 32

// Per-column packed argmax accumulators, updated with atomicMax.
// key = (float_bits(|v|max) << 32) | ~t : u64 max -> larger |v| wins; on ties
// the larger ~t (= smaller t) wins, matching jnp.argmax. keys are always > 0,
// so a zeroed accumulator is a valid identity. The epilogue self-resets all
// state, so every graph replay starts clean.
__device__ unsigned long long g_bx[NCOL];
__device__ unsigned long long g_by[NCOL];
__device__ unsigned int       g_done;

// Single kernel: grid (XBLK, NSEG) = 640 blocks, 163,840 threads.
// Thread (cg, seg) scans SEG_LEN=50 time samples of 4 adjacent columns
// (float4, streaming loads) for both x and y; every warp load covers 512B of
// contiguous lines. Ticketed last block runs the MSE epilogue from L2.
__global__ __launch_bounds__(TPB) void traveltime_kernel(
    const float* __restrict__ x, const float* __restrict__ y,
    float* __restrict__ out)
{
    const int cg  = blockIdx.x * TPB + threadIdx.x;   // 0..NCG-1
    const int seg = blockIdx.y;                       // 0..NSEG-1
    const int t0  = seg * SEG_LEN;

    const float4* __restrict__ px = (const float4*)x + (size_t)t0 * NCG + cg;
    const float4* __restrict__ py = (const float4*)y + (size_t)t0 * NCG + cg;

    float mx0 = -1.f, mx1 = -1.f, mx2 = -1.f, mx3 = -1.f;
    float my0 = -1.f, my1 = -1.f, my2 = -1.f, my3 = -1.f;
    int ix0 = t0, ix1 = t0, ix2 = t0, ix3 = t0;
    int iy0 = t0, iy1 = t0, iy2 = t0, iy3 = t0;

    #pragma unroll 5
    for (int i = 0; i < SEG_LEN; ++i) {
        const float4 vx = __ldcs(px + (size_t)i * NCG);  // evict-first stream
        const float4 vy = __ldcs(py + (size_t)i * NCG);
        const int t = t0 + i;

        if (fabsf(vx.x) > mx0) ix0 = t; mx0 = fmaxf(fabsf(vx.x), mx0);
        if (fabsf(vx.y) > mx1) ix1 = t; mx1 = fmaxf(fabsf(vx.y), mx1);
        if (fabsf(vx.z) > mx2) ix2 = t; mx2 = fmaxf(fabsf(vx.z), mx2);
        if (fabsf(vx.w) > mx3) ix3 = t; mx3 = fmaxf(fabsf(vx.w), mx3);

        if (fabsf(vy.x) > my0) iy0 = t; my0 = fmaxf(fabsf(vy.x), my0);
        if (fabsf(vy.y) > my1) iy1 = t; my1 = fmaxf(fabsf(vy.y), my1);
        if (fabsf(vy.z) > my2) iy2 = t; my2 = fmaxf(fabsf(vy.z), my2);
        if (fabsf(vy.w) > my3) iy3 = t; my3 = fmaxf(fabsf(vy.w), my3);
    }

    const int colb = 4 * cg;
    atomicMax(&g_bx[colb + 0],
        ((unsigned long long)__float_as_uint(mx0) << 32) | (unsigned int)~ix0);
    atomicMax(&g_bx[colb + 1],
        ((unsigned long long)__float_as_uint(mx1) << 32) | (unsigned int)~ix1);
    atomicMax(&g_bx[colb + 2],
        ((unsigned long long)__float_as_uint(mx2) << 32) | (unsigned int)~ix2);
    atomicMax(&g_bx[colb + 3],
        ((unsigned long long)__float_as_uint(mx3) << 32) | (unsigned int)~ix3);
    atomicMax(&g_by[colb + 0],
        ((unsigned long long)__float_as_uint(my0) << 32) | (unsigned int)~iy0);
    atomicMax(&g_by[colb + 1],
        ((unsigned long long)__float_as_uint(my1) << 32) | (unsigned int)~iy1);
    atomicMax(&g_by[colb + 2],
        ((unsigned long long)__float_as_uint(my2) << 32) | (unsigned int)~iy2);
    atomicMax(&g_by[colb + 3],
        ((unsigned long long)__float_as_uint(my3) << 32) | (unsigned int)~iy3);

    // ---- Ticketed epilogue: only the last block to finish proceeds. ----
    __threadfence();            // make this thread's atomics globally visible
    __syncthreads();            // all threads in block done + fenced

    __shared__ bool s_last;
    if (threadIdx.x == 0)
        s_last = (atomicAdd(&g_done, 1u) == (unsigned int)(NBLK - 1));
    __syncthreads();
    if (!s_last) return;

    __threadfence();            // acquire: see all other blocks' atomics

    // 256 threads, 32 columns each (coalesced). Reads hit L2 (atomics live
    // there). Self-reset the accumulators for the next graph replay.
    unsigned long long sum = 0ull;
    #pragma unroll
    for (int k = 0; k < COLS_PER_THREAD; ++k) {
        const int col = k * TPB + threadIdx.x;
        const unsigned long long bx = g_bx[col];
        const unsigned long long by = g_by[col];
        g_bx[col] = 0ull;
        g_by[col] = 0ull;
        const int tx = (int)(~(unsigned int)bx);
        const int ty = (int)(~(unsigned int)by);
        const long long d = (long long)tx - (long long)ty;
        sum += (unsigned long long)(d * d);
    }

    #pragma unroll
    for (int off = 16; off > 0; off >>= 1)
        sum += __shfl_down_sync(0xffffffffu, sum, off);

    __shared__ unsigned long long warp_sums[TPB / 32];
    const int lane = threadIdx.x & 31;
    const int wid  = threadIdx.x >> 5;
    if (lane == 0) warp_sums[wid] = sum;
    __syncthreads();

    if (wid == 0) {
        unsigned long long v = (lane < TPB / 32) ? warp_sums[lane] : 0ull;
        #pragma unroll
        for (int off = 4; off > 0; off >>= 1)
            v += __shfl_down_sync(0xffffffffu, v, off);
        if (lane == 0) {
            out[0] = (float)((double)v / (double)NCOL);
            __threadfence();
            g_done = 0u;        // reset ticket for the next graph replay
        }
    }
}

extern "C" void kernel_launch(void* const* d_in, const int* in_sizes, int n_in,
                              void* d_out, int out_size)
{
    const float* x = (const float*)d_in[0];
    const float* y = (const float*)d_in[1];
    float* out = (float*)d_out;

    dim3 grid(XBLK, NSEG);
    traveltime_kernel<<<grid, TPB>>>(x, y, out);
}